// round 5
// baseline (speedup 1.0000x reference)
#include <cuda_runtime.h>
#include <cstdint>

#define B_    256
#define N_    32
#define DH_   128
#define E_    496
#define KH    256     // DIM_HID
#define NO    96      // DIM_OUT
#define AOUT  12
#define ETILE 62      // edges per block (496 = 8*62)
#define MROWS 128     // 2*ETILE=124 padded to 128
#define LDH   257     // hs row pitch (bank-conflict-free for tm stride 4*257%32=4)
#define LDP   97      // P row pitch
#define JTILE 64
#define LDW1  257

// -------- device scratch (no allocation allowed) --------
__device__ float g_u[2u * B_ * N_ * KH];   // [s][b][n][k], 16 MB
__device__ float g_w2t[KH * NO];           // W2 transposed to [k][n]
__device__ int   g_ef[E_], g_et[E_];

// -------- f32x2 helpers --------
__device__ __forceinline__ unsigned long long pk2(float x) {
    unsigned long long r;
    asm("mov.b64 %0, {%1,%2};" : "=l"(r) : "f"(x), "f"(x));
    return r;
}
__device__ __forceinline__ void ffma2(unsigned long long& d,
                                      unsigned long long a,
                                      unsigned long long b) {
    asm("fma.rn.f32x2 %0, %1, %2, %0;" : "+l"(d) : "l"(a), "l"(b));
}
__device__ __forceinline__ float2 upk(unsigned long long v) {
    float2 r;
    asm("mov.b64 {%0,%1}, %2;" : "=f"(r.x), "=f"(r.y) : "l"(v));
    return r;
}

// -------- prep: normalize edge dtype (int32 vs int64) --------
__global__ void prep_edges(const int* __restrict__ efw, const int* __restrict__ etw) {
    int bad = 0;
    // words 0..E_-1 are in-bounds for both int32 (E_ words) and int64 (2E_ words)
    for (int t = threadIdx.x; t < E_; t += blockDim.x)
        if (t & 1)
            if (efw[t] != 0 || etw[t] != 0) bad = 1;
    int is32 = __syncthreads_or(bad);   // any nonzero odd word => int32
    for (int e = threadIdx.x; e < E_; e += blockDim.x) {
        g_ef[e] = is32 ? efw[e] : efw[2 * e];
        g_et[e] = is32 ? etw[e] : etw[2 * e];
    }
}

// -------- prep: transpose W2 [n][k] -> [k][n] (tiny, 98 KB) --------
__global__ void transpose_w2(const float* __restrict__ W2) {
    int idx = blockIdx.x * 256 + threadIdx.x;   // 0..24575
    if (idx < KH * NO) {
        int k = idx / NO;
        int n = idx - k * NO;
        g_w2t[idx] = W2[n * KH + k];            // write coalesced
    }
}

// -------- stage A: per-node projections u1 = h@W1[:, :128].T, u2 = h@W1[:,128:].T --------
__global__ void __launch_bounds__(256) node_proj(const float* __restrict__ h,
                                                 const float* __restrict__ W1) {
    extern __shared__ float sm[];
    float* hsA = sm;                    // 32*128
    float* w1s = sm + N_ * DH_;         // 64*LDW1

    int b  = blockIdx.y;
    int j0 = blockIdx.x * JTILE;
    int tid = threadIdx.x;

    for (int i = tid; i < N_ * DH_; i += 256)
        hsA[i] = h[(size_t)b * N_ * DH_ + i];
    for (int i = tid; i < JTILE * 256; i += 256) {
        int r = i >> 8, c = i & 255;
        w1s[r * LDW1 + c] = W1[(size_t)(j0 + r) * 256 + c];
    }
    __syncthreads();

    int jl = tid & 63;      // warp-aligned: lanes have distinct jl -> stride-257 conflict-free
    int ng = tid >> 6;      // node group (8 nodes)
    float acc1[8], acc2[8];
#pragma unroll
    for (int i = 0; i < 8; i++) { acc1[i] = 0.f; acc2[i] = 0.f; }

    const float* w1row = &w1s[jl * LDW1];
    const float* hbase = &hsA[ng * 8 * DH_];
#pragma unroll 4
    for (int k = 0; k < DH_; k++) {
        float wa = w1row[k];
        float wb = w1row[k + 128];
#pragma unroll
        for (int nn = 0; nn < 8; nn++) {
            float hv = hbase[nn * DH_ + k];     // broadcast within warp
            acc1[nn] = fmaf(wa, hv, acc1[nn]);
            acc2[nn] = fmaf(wb, hv, acc2[nn]);
        }
    }
    int j = j0 + jl;
#pragma unroll
    for (int nn = 0; nn < 8; nn++) {
        int n = ng * 8 + nn;
        g_u[(size_t)(b * N_ + n) * KH + j] = acc1[nn];
        g_u[(size_t)B_ * N_ * KH + (size_t)(b * N_ + n) * KH + j] = acc2[nn];
    }
}

// -------- stage B: fused hidden build + GEMM2 (f32x2) + payoff einsum --------
__global__ void __launch_bounds__(256) edge_gemm(const float* __restrict__ b1,
                                                 const float* __restrict__ b2,
                                                 float* __restrict__ out) {
    extern __shared__ float sm[];
    float* hs  = sm;                        // MROWS * LDH
    float* w2s = sm + MROWS * LDH;          // KH * NO  (reused as Ps after GEMM)
    float* Ps  = w2s;
    __shared__ int s_ef[ETILE], s_et[ETILE];

    int b   = blockIdx.y;
    int e0  = blockIdx.x * ETILE;
    int tid = threadIdx.x;

    if (tid < ETILE) { s_ef[tid] = g_ef[e0 + tid]; s_et[tid] = g_et[e0 + tid]; }
    for (int i = tid; i < KH * NO; i += 256) w2s[i] = g_w2t[i];   // coalesced both sides
    __syncthreads();

    // build h tile: rows 0..61 = s0 (u1[f]+u2[t]), rows 62..123 = s1 (u1[t]+u2[f])
    const float* u1b = &g_u[(size_t)(b * N_) * KH];
    const float* u2b = &g_u[(size_t)B_ * N_ * KH + (size_t)(b * N_) * KH];
    float b1k = b1[tid];                    // tid == k
#pragma unroll 4
    for (int m = 0; m < 2 * ETILE; m++) {
        int el = (m < ETILE) ? m : m - ETILE;
        int nf, nt;
        if (m < ETILE) { nf = s_ef[el]; nt = s_et[el]; }
        else           { nf = s_et[el]; nt = s_ef[el]; }
        float v = u1b[nf * KH + tid] + u2b[nt * KH + tid] + b1k;
        hs[m * LDH + tid] = fmaxf(v, 0.f);
    }
#pragma unroll
    for (int m = 2 * ETILE; m < MROWS; m++) hs[m * LDH + tid] = 0.f;  // pad rows
    __syncthreads();

    // GEMM: M=128, N=96, K=256; thread tile 4 rows x 12 cols (6 f32x2)
    int tn = tid & 7;       // column group: cols tn*12 .. tn*12+11
    int tm = tid >> 3;      // row group:    rows tm*4 .. tm*4+3
    unsigned long long acc[4][6];
#pragma unroll
    for (int r = 0; r < 4; r++)
#pragma unroll
        for (int q = 0; q < 6; q++) acc[r][q] = 0ull;

    const float* ar = &hs[(tm * 4) * LDH];
    const unsigned long long* wbase =
        reinterpret_cast<const unsigned long long*>(&w2s[tn * 12]);  // 48B-aligned

#pragma unroll 4
    for (int k = 0; k < KH; k++) {
        unsigned long long w[6];
        const unsigned long long* wk = wbase + (size_t)k * (NO / 2);
#pragma unroll
        for (int q = 0; q < 6; q++) w[q] = wk[q];     // LDS.64, banks {0,12,24,4,16,28,8,20}
#pragma unroll
        for (int r = 0; r < 4; r++) {
            unsigned long long A = pk2(ar[r * LDH + k]);  // 4 tm-banks 0/4/8/12 apart
#pragma unroll
            for (int q = 0; q < 6; q++) ffma2(acc[r][q], A, w[q]);
        }
    }

    // epilogue: + b2, unpack
    const float2* b2v = reinterpret_cast<const float2*>(b2);
    float2 pv[4][6];
#pragma unroll
    for (int r = 0; r < 4; r++)
#pragma unroll
        for (int q = 0; q < 6; q++) {
            float2 v = upk(acc[r][q]);
            float2 bb = b2v[tn * 6 + q];
            v.x += bb.x; v.y += bb.y;
            pv[r][q] = v;
        }

    __syncthreads();    // all threads done reading w2s/hs
#pragma unroll
    for (int r = 0; r < 4; r++) {
        int m = tm * 4 + r;
        if (m < 2 * ETILE) {
#pragma unroll
            for (int q = 0; q < 6; q++) {
                Ps[m * LDP + tn * 12 + 2 * q]     = pv[r][q].x;
                Ps[m * LDP + tn * 12 + 2 * q + 1] = pv[r][q].y;
            }
        }
    }
    __syncthreads();

    // payoff: out[b,e,i,j] = 0.5*( sum_r P0[24r+i]*P0[24r+12+j] + sum_r P1[24r+j]*P1[24r+12+i] )
    for (int pr = tid; pr < ETILE * AOUT; pr += 256) {
        int el = pr / AOUT;
        int i  = pr - el * AOUT;
        const float* P0 = &Ps[el * LDP];
        const float* P1 = &Ps[(ETILE + el) * LDP];
        float a0[4], a1[4];
#pragma unroll
        for (int r = 0; r < 4; r++) {
            a0[r] = P0[24 * r + i];
            a1[r] = P1[24 * r + 12 + i];
        }
        float res[12];
#pragma unroll
        for (int j = 0; j < 12; j++) {
            float s = 0.f;
#pragma unroll
            for (int r = 0; r < 4; r++)
                s = fmaf(a0[r], P0[24 * r + 12 + j], fmaf(a1[r], P1[24 * r + j], s));
            res[j] = 0.5f * s;
        }
        float4* op = reinterpret_cast<float4*>(
            out + ((size_t)(b * E_ + e0 + el) * AOUT + i) * AOUT);
        op[0] = make_float4(res[0], res[1], res[2],  res[3]);
        op[1] = make_float4(res[4], res[5], res[6],  res[7]);
        op[2] = make_float4(res[8], res[9], res[10], res[11]);
    }
}

// -------- launch --------
extern "C" void kernel_launch(void* const* d_in, const int* in_sizes, int n_in,
                              void* d_out, int out_size) {
    const float* h  = (const float*)d_in[0];
    const float* W1 = (const float*)d_in[1];
    const float* b1 = (const float*)d_in[2];
    const float* W2 = (const float*)d_in[3];
    const float* b2 = (const float*)d_in[4];
    const int*   ef = (const int*)d_in[5];
    const int*   et = (const int*)d_in[6];
    float* out = (float*)d_out;

    const int SMEM_A = (N_ * DH_ + JTILE * LDW1) * 4;      // 82,176 B
    const int SMEM_B = (MROWS * LDH + KH * NO) * 4;        // 229,888 B

    cudaFuncSetAttribute(node_proj, cudaFuncAttributeMaxDynamicSharedMemorySize, SMEM_A);
    cudaFuncSetAttribute(edge_gemm, cudaFuncAttributeMaxDynamicSharedMemorySize, SMEM_B);

    prep_edges<<<1, 256>>>(ef, et);
    transpose_w2<<<(KH * NO + 255) / 256, 256>>>(W2);
    node_proj<<<dim3(KH / JTILE, B_), 256, SMEM_A>>>(h, W1);
    edge_gemm<<<dim3(E_ / ETILE, B_), 256, SMEM_B>>>(b1, b2, out);
}

// round 6
// speedup vs baseline: 1.3717x; 1.3717x over previous
#include <cuda_runtime.h>
#include <cstdint>

#define B_    256
#define N_    32
#define DH_   128
#define E_    496
#define KH    256     // DIM_HID
#define NO    96      // DIM_OUT
#define AOUT  12
#define ETILE 62      // edges per block (496 = 8*62)
#define MROWS 128     // 2*ETILE=124 padded to 128
#define LDH   257     // hs row pitch
#define LDP   97      // P row pitch
#define JTILE 64
#define LDW1  257

// -------- device scratch (no allocation allowed) --------
__device__ float g_u[2u * B_ * N_ * KH];   // [s][b][n][k], 16 MB
__device__ float g_w2t[KH * NO];           // W2 transposed to [k][n]
__device__ int   g_ef[E_], g_et[E_];

// -------- f32x2 helpers --------
__device__ __forceinline__ unsigned long long pk2(float x) {
    unsigned long long r;
    asm("mov.b64 %0, {%1,%2};" : "=l"(r) : "f"(x), "f"(x));
    return r;
}
__device__ __forceinline__ void ffma2(unsigned long long& d,
                                      unsigned long long a,
                                      unsigned long long b) {
    asm("fma.rn.f32x2 %0, %1, %2, %0;" : "+l"(d) : "l"(a), "l"(b));
}
__device__ __forceinline__ float2 upk(unsigned long long v) {
    float2 r;
    asm("mov.b64 {%0,%1}, %2;" : "=f"(r.x), "=f"(r.y) : "l"(v));
    return r;
}

// -------- prep: normalize edge dtype (int32 vs int64) --------
__global__ void prep_edges(const int* __restrict__ efw, const int* __restrict__ etw) {
    int bad = 0;
    for (int t = threadIdx.x; t < E_; t += blockDim.x)
        if (t & 1)
            if (efw[t] != 0 || etw[t] != 0) bad = 1;
    int is32 = __syncthreads_or(bad);   // any nonzero odd word => int32
    for (int e = threadIdx.x; e < E_; e += blockDim.x) {
        g_ef[e] = is32 ? efw[e] : efw[2 * e];
        g_et[e] = is32 ? etw[e] : etw[2 * e];
    }
}

// -------- prep: transpose W2 [n][k] -> [k][n] --------
__global__ void transpose_w2(const float* __restrict__ W2) {
    int idx = blockIdx.x * 256 + threadIdx.x;
    if (idx < KH * NO) {
        int k = idx / NO;
        int n = idx - k * NO;
        g_w2t[idx] = W2[n * KH + k];
    }
}

// -------- stage A: per-node projections --------
__global__ void __launch_bounds__(256) node_proj(const float* __restrict__ h,
                                                 const float* __restrict__ W1) {
    extern __shared__ float sm[];
    float* hsA = sm;                    // 32*128
    float* w1s = sm + N_ * DH_;         // 64*LDW1

    int b  = blockIdx.y;
    int j0 = blockIdx.x * JTILE;
    int tid = threadIdx.x;

    for (int i = tid; i < N_ * DH_; i += 256)
        hsA[i] = h[(size_t)b * N_ * DH_ + i];
    for (int i = tid; i < JTILE * 256; i += 256) {
        int r = i >> 8, c = i & 255;
        w1s[r * LDW1 + c] = W1[(size_t)(j0 + r) * 256 + c];
    }
    __syncthreads();

    int jl = tid & 63;
    int ng = tid >> 6;
    float acc1[8], acc2[8];
#pragma unroll
    for (int i = 0; i < 8; i++) { acc1[i] = 0.f; acc2[i] = 0.f; }

    const float* w1row = &w1s[jl * LDW1];
    const float* hbase = &hsA[ng * 8 * DH_];
#pragma unroll 4
    for (int k = 0; k < DH_; k++) {
        float wa = w1row[k];
        float wb = w1row[k + 128];
#pragma unroll
        for (int nn = 0; nn < 8; nn++) {
            float hv = hbase[nn * DH_ + k];
            acc1[nn] = fmaf(wa, hv, acc1[nn]);
            acc2[nn] = fmaf(wb, hv, acc2[nn]);
        }
    }
    int j = j0 + jl;
#pragma unroll
    for (int nn = 0; nn < 8; nn++) {
        int n = ng * 8 + nn;
        g_u[(size_t)(b * N_ + n) * KH + j] = acc1[nn];
        g_u[(size_t)B_ * N_ * KH + (size_t)(b * N_ + n) * KH + j] = acc2[nn];
    }
}

// -------- stage B: fused hidden build + GEMM2 (512 thr, K-split 2) + payoff --------
__global__ void __launch_bounds__(512) edge_gemm(const float* __restrict__ b1,
                                                 const float* __restrict__ b2,
                                                 float* __restrict__ out) {
    extern __shared__ float sm[];
    float* hs  = sm;                        // MROWS * LDH
    float* w2s = sm + MROWS * LDH;          // KH * NO  (reused as Ps after GEMM)
    float* Ps  = w2s;
    __shared__ int s_ef[ETILE], s_et[ETILE];
    __shared__ float s_b1[KH];

    int b   = blockIdx.y;
    int e0  = blockIdx.x * ETILE;
    int tid = threadIdx.x;

    if (tid < ETILE) { s_ef[tid] = g_ef[e0 + tid]; s_et[tid] = g_et[e0 + tid]; }
    if (tid < KH)    s_b1[tid] = b1[tid];
    for (int i = tid; i < KH * NO; i += 512) w2s[i] = g_w2t[i];
    __syncthreads();

    // build h tile: rows 0..61 = s0 (u1[f]+u2[t]), rows 62..123 = s1 (u1[t]+u2[f])
    const float* u1b = &g_u[(size_t)(b * N_) * KH];
    const float* u2b = &g_u[(size_t)B_ * N_ * KH + (size_t)(b * N_) * KH];
    for (int i = tid; i < 2 * ETILE * KH; i += 512) {
        int m = i >> 8;          // 0..123
        int k = i & 255;
        int el = (m < ETILE) ? m : m - ETILE;
        int nf, nt;
        if (m < ETILE) { nf = s_ef[el]; nt = s_et[el]; }
        else           { nf = s_et[el]; nt = s_ef[el]; }
        float v = u1b[nf * KH + k] + u2b[nt * KH + k] + s_b1[k];
        hs[m * LDH + k] = fmaxf(v, 0.f);
    }
    for (int i = tid; i < (MROWS - 2 * ETILE) * KH; i += 512) {
        int m = 2 * ETILE + (i >> 8);
        hs[m * LDH + (i & 255)] = 0.f;
    }
    __syncthreads();

    // GEMM: M=128, N=96, K=256. 512 threads: K-split 2, thread tile 4 rows x 12 cols.
    int half = tid >> 8;     // 0: k in [0,128), 1: k in [128,256)
    int r8   = tid & 255;
    int tn   = r8 & 7;       // column group: cols tn*12 .. tn*12+11
    int tm   = r8 >> 3;      // row group:    rows tm*4 .. tm*4+3
    int k0   = half * (KH / 2);

    unsigned long long acc[4][6];
#pragma unroll
    for (int r = 0; r < 4; r++)
#pragma unroll
        for (int q = 0; q < 6; q++) acc[r][q] = 0ull;

    const float* ar = &hs[(tm * 4) * LDH + k0];
    const unsigned long long* wbase =
        reinterpret_cast<const unsigned long long*>(&w2s[tn * 12]) +
        (size_t)k0 * (NO / 2);

#pragma unroll 4
    for (int k = 0; k < KH / 2; k++) {
        unsigned long long w[6];
        const unsigned long long* wk = wbase + (size_t)k * (NO / 2);
#pragma unroll
        for (int q = 0; q < 6; q++) w[q] = wk[q];     // LDS.64, conflict-free bank set
#pragma unroll
        for (int r = 0; r < 4; r++) {
            unsigned long long A = pk2(ar[r * LDH + k]);
#pragma unroll
            for (int q = 0; q < 6; q++) ffma2(acc[r][q], A, w[q]);
        }
    }

    __syncthreads();    // all reads of w2s done before Ps overwrite

    // reduction: half 0 writes partials, half 1 adds its partials + b2
    if (half == 0) {
#pragma unroll
        for (int r = 0; r < 4; r++) {
            int m = tm * 4 + r;
            if (m < 2 * ETILE) {
#pragma unroll
                for (int q = 0; q < 6; q++) {
                    float2 v = upk(acc[r][q]);
                    Ps[m * LDP + tn * 12 + 2 * q]     = v.x;
                    Ps[m * LDP + tn * 12 + 2 * q + 1] = v.y;
                }
            }
        }
    }
    __syncthreads();
    if (half == 1) {
        const float2* b2v = reinterpret_cast<const float2*>(b2);
#pragma unroll
        for (int r = 0; r < 4; r++) {
            int m = tm * 4 + r;
            if (m < 2 * ETILE) {
#pragma unroll
                for (int q = 0; q < 6; q++) {
                    float2 v = upk(acc[r][q]);
                    float2 bb = b2v[tn * 6 + q];
                    float* p = &Ps[m * LDP + tn * 12 + 2 * q];
                    p[0] = p[0] + v.x + bb.x;
                    p[1] = p[1] + v.y + bb.y;
                }
            }
        }
    }
    __syncthreads();

    // payoff: out[b,e,i,j] = 0.5*( sum_r P0[24r+i]*P0[24r+12+j] + sum_r P1[24r+j]*P1[24r+12+i] )
    for (int pr = tid; pr < ETILE * AOUT; pr += 512) {
        int el = pr / AOUT;
        int i  = pr - el * AOUT;
        const float* P0 = &Ps[el * LDP];
        const float* P1 = &Ps[(ETILE + el) * LDP];
        float a0[4], a1[4];
#pragma unroll
        for (int r = 0; r < 4; r++) {
            a0[r] = P0[24 * r + i];
            a1[r] = P1[24 * r + 12 + i];
        }
        float res[12];
#pragma unroll
        for (int j = 0; j < 12; j++) {
            float s = 0.f;
#pragma unroll
            for (int r = 0; r < 4; r++)
                s = fmaf(a0[r], P0[24 * r + 12 + j], fmaf(a1[r], P1[24 * r + j], s));
            res[j] = 0.5f * s;
        }
        float4* op = reinterpret_cast<float4*>(
            out + ((size_t)(b * E_ + e0 + el) * AOUT + i) * AOUT);
        op[0] = make_float4(res[0], res[1], res[2],  res[3]);
        op[1] = make_float4(res[4], res[5], res[6],  res[7]);
        op[2] = make_float4(res[8], res[9], res[10], res[11]);
    }
}

// -------- launch --------
extern "C" void kernel_launch(void* const* d_in, const int* in_sizes, int n_in,
                              void* d_out, int out_size) {
    const float* h  = (const float*)d_in[0];
    const float* W1 = (const float*)d_in[1];
    const float* b1 = (const float*)d_in[2];
    const float* W2 = (const float*)d_in[3];
    const float* b2 = (const float*)d_in[4];
    const int*   ef = (const int*)d_in[5];
    const int*   et = (const int*)d_in[6];
    float* out = (float*)d_out;

    const int SMEM_A = (N_ * DH_ + JTILE * LDW1) * 4;      // 82,176 B
    const int SMEM_B = (MROWS * LDH + KH * NO) * 4;        // 229,888 B

    cudaFuncSetAttribute(node_proj, cudaFuncAttributeMaxDynamicSharedMemorySize, SMEM_A);
    cudaFuncSetAttribute(edge_gemm, cudaFuncAttributeMaxDynamicSharedMemorySize, SMEM_B);

    prep_edges<<<1, 256>>>(ef, et);
    transpose_w2<<<(KH * NO + 255) / 256, 256>>>(W2);
    node_proj<<<dim3(KH / JTILE, B_), 256, SMEM_A>>>(h, W1);
    edge_gemm<<<dim3(E_ / ETILE, B_), 512, SMEM_B>>>(b1, b2, out);
}

// round 8
// speedup vs baseline: 2.3787x; 1.7341x over previous
#include <cuda_runtime.h>
#include <cuda_bf16.h>
#include <cstdint>

#define B_    256
#define N_    32
#define DH_   128
#define E_    496
#define KH    256     // DIM_HID
#define NO    96      // DIM_OUT
#define AOUT  12
#define ETILE 62      // edges per block
#define MR    124     // 2*ETILE real rows
#define PA    1040    // A row pitch bytes: 128 kp-cells * 8B + 16 pad
#define PB    1040    // B row pitch bytes
#define LDP   98      // Ps pitch (even -> float2 aligned)
#define JTILE 64
#define LDW1  257

#define A_REGION (MR * PA)               // 128,960
#define B_REGION (NO * PB)               // 99,840
#define SMEM_EDGE (A_REGION + B_REGION)  // 228,800

// -------- device scratch --------
__device__ float g_u[2u * B_ * N_ * KH];       // [s][b][n][k]; s0 plane has +b1 folded
__device__ unsigned char g_w2i[NO * KH * 4];   // W2 interleaved hi/lo bf16: [n][kp]{hi0,hi1,lo0,lo1}
__device__ int g_ef[E_], g_et[E_];

// -------- mma.sync helper (bf16, f32 accum) --------
__device__ __forceinline__ void mma16816(float* c,
                                         uint32_t a0, uint32_t a1, uint32_t a2, uint32_t a3,
                                         uint32_t b0, uint32_t b1) {
    asm volatile(
        "mma.sync.aligned.m16n8k16.row.col.f32.bf16.bf16.f32 "
        "{%0,%1,%2,%3}, {%4,%5,%6,%7}, {%8,%9}, {%0,%1,%2,%3};"
        : "+f"(c[0]), "+f"(c[1]), "+f"(c[2]), "+f"(c[3])
        : "r"(a0), "r"(a1), "r"(a2), "r"(a3), "r"(b0), "r"(b1));
}

// -------- prep: normalize edge dtype (int32 vs int64) --------
__global__ void prep_edges(const int* __restrict__ efw, const int* __restrict__ etw) {
    int bad = 0;
    for (int t = threadIdx.x; t < E_; t += blockDim.x)
        if (t & 1)
            if (efw[t] != 0 || etw[t] != 0) bad = 1;
    int is32 = __syncthreads_or(bad);
    for (int e = threadIdx.x; e < E_; e += blockDim.x) {
        g_ef[e] = is32 ? efw[e] : efw[2 * e];
        g_et[e] = is32 ? etw[e] : etw[2 * e];
    }
}

// -------- prep: W2 -> interleaved hi/lo bf16 cells --------
__global__ void prep_w2(const float* __restrict__ W2) {
    int idx = blockIdx.x * 256 + threadIdx.x;    // n*256 + k
    if (idx >= NO * KH) return;
    int n = idx >> 8, k = idx & 255;
    float v = W2[idx];
    __nv_bfloat16 hi = __float2bfloat16(v);
    __nv_bfloat16 lo = __float2bfloat16(v - __bfloat162float(hi));
    uint32_t cell = (uint32_t)n * 1024 + (uint32_t)(k >> 1) * 8 + (uint32_t)(k & 1) * 2;
    *(__nv_bfloat16*)(g_w2i + cell)     = hi;
    *(__nv_bfloat16*)(g_w2i + cell + 4) = lo;
}

// -------- stage A: node projections (b1 folded into u1 plane) --------
__global__ void __launch_bounds__(256) node_proj(const float* __restrict__ h,
                                                 const float* __restrict__ W1,
                                                 const float* __restrict__ b1) {
    extern __shared__ float smf[];
    float* hsA = smf;                   // 32*128
    float* w1s = smf + N_ * DH_;        // 64*LDW1

    int b  = blockIdx.y;
    int j0 = blockIdx.x * JTILE;
    int tid = threadIdx.x;

    for (int i = tid; i < N_ * DH_; i += 256)
        hsA[i] = h[(size_t)b * N_ * DH_ + i];
    for (int i = tid; i < JTILE * 256; i += 256) {
        int r = i >> 8, c = i & 255;
        w1s[r * LDW1 + c] = W1[(size_t)(j0 + r) * 256 + c];
    }
    __syncthreads();

    int jl = tid & 63;
    int ng = tid >> 6;
    float acc1[8], acc2[8];
#pragma unroll
    for (int i = 0; i < 8; i++) { acc1[i] = 0.f; acc2[i] = 0.f; }

    const float* w1row = &w1s[jl * LDW1];
    const float* hbase = &hsA[ng * 8 * DH_];
#pragma unroll 4
    for (int k = 0; k < DH_; k++) {
        float wa = w1row[k];
        float wb = w1row[k + 128];
#pragma unroll
        for (int nn = 0; nn < 8; nn++) {
            float hv = hbase[nn * DH_ + k];
            acc1[nn] = fmaf(wa, hv, acc1[nn]);
            acc2[nn] = fmaf(wb, hv, acc2[nn]);
        }
    }
    int j = j0 + jl;
    float b1v = b1[j];
#pragma unroll
    for (int nn = 0; nn < 8; nn++) {
        int n = ng * 8 + nn;
        g_u[(size_t)(b * N_ + n) * KH + j] = acc1[nn] + b1v;
        g_u[(size_t)B_ * N_ * KH + (size_t)(b * N_ + n) * KH + j] = acc2[nn];
    }
}

// -------- stage B: HMMA bf16x3 GEMM + payoff --------
__global__ void __launch_bounds__(512, 1) edge_gemm(const float* __restrict__ b2,
                                                    float* __restrict__ out) {
    extern __shared__ unsigned char sm[];
    unsigned char* Asm = sm;                    // MR * PA  (interleaved hi/lo A)
    unsigned char* Bsm = sm + A_REGION;         // NO * PB  (interleaved hi/lo B)
    float* su1 = (float*)Bsm;                   // u staging lives in B region pre-copy
    float* su2 = su1 + N_ * KH;
    float* Ps  = (float*)Asm;                   // P result reuses A region post-MMA

    __shared__ int s_ef[ETILE], s_et[ETILE];
    __shared__ float s_b2[NO];

    int b = blockIdx.y, e0 = blockIdx.x * ETILE;
    int tid = threadIdx.x;
    int wid = tid >> 5, lid = tid & 31;

    if (tid < ETILE) { s_ef[tid] = g_ef[e0 + tid]; s_et[tid] = g_et[e0 + tid]; }
    if (tid >= 128 && tid < 128 + NO) s_b2[tid - 128] = b2[tid - 128];

    // ---- stage u planes into SMEM (coalesced) ----
    {
        const float4* gp1 = (const float4*)(g_u + (size_t)b * N_ * KH);
        const float4* gp2 = (const float4*)(g_u + (size_t)B_ * N_ * KH + (size_t)b * N_ * KH);
        float4* d1 = (float4*)su1;
        float4* d2 = (float4*)su2;
        for (int i = tid; i < N_ * KH / 4; i += 512) { d1[i] = gp1[i]; d2[i] = gp2[i]; }
    }
    __syncthreads();

    // ---- build A: relu(u1[f]+u2[t]) -> interleaved hi/lo bf16 cells ----
    for (int i = tid; i < MR * (KH / 2); i += 512) {
        int m = i >> 7, kp = i & 127;
        int el = (m < ETILE) ? m : m - ETILE;
        int nf, nt;
        if (m < ETILE) { nf = s_ef[el]; nt = s_et[el]; }
        else           { nf = s_et[el]; nt = s_ef[el]; }
        float2 ua = *(const float2*)(su1 + nf * KH + 2 * kp);
        float2 ub = *(const float2*)(su2 + nt * KH + 2 * kp);
        float v0 = fmaxf(ua.x + ub.x, 0.f), v1 = fmaxf(ua.y + ub.y, 0.f);
        __nv_bfloat16 h0 = __float2bfloat16(v0), h1 = __float2bfloat16(v1);
        float r0 = v0 - __bfloat162float(h0), r1 = v1 - __bfloat162float(h1);
        __nv_bfloat16 l0 = __float2bfloat16(r0), l1 = __float2bfloat16(r1);
        uint2 cell;
        cell.x = ((uint32_t)__bfloat16_as_ushort(h1) << 16) | __bfloat16_as_ushort(h0);
        cell.y = ((uint32_t)__bfloat16_as_ushort(l1) << 16) | __bfloat16_as_ushort(l0);
        *(uint2*)(Asm + (uint32_t)m * PA + (uint32_t)kp * 8) = cell;
    }
    __syncthreads();    // A built before u staging area is overwritten by B

    // ---- copy B (pre-interleaved) global -> SMEM with pitch ----
    for (int i = tid; i < NO * 64; i += 512) {       // 64 x 16B per row
        int n = i >> 6, c = i & 63;
        *(float4*)(Bsm + (uint32_t)n * PB + (uint32_t)c * 16) =
            *(const float4*)(g_w2i + (uint32_t)n * 1024 + (uint32_t)c * 16);
    }
    __syncthreads();

    // ---- HMMA: warp tile m32 x n48, K-split 2 (halves reduce via smem) ----
    int half = wid >> 3;            // k half
    int wl   = wid & 7;
    int m0   = (wl >> 1) * 32;
    int n0   = (wl & 1) * 48;
    int lr   = lid >> 2;            // 0..7
    int lc   = lid & 3;             // 0..3

    float acc[2][6][4];
#pragma unroll
    for (int fr = 0; fr < 2; fr++)
#pragma unroll
        for (int t = 0; t < 6; t++)
#pragma unroll
            for (int q = 0; q < 4; q++) acc[fr][t][q] = 0.f;

    uint32_t aoff = (uint32_t)(m0 + lr) * PA + (uint32_t)lc * 8;
    uint32_t boff = (uint32_t)(n0 + lr) * PB + (uint32_t)lc * 8;
    uint32_t kb0  = (uint32_t)half * 512;     // 64 kp-cells * 8B

#pragma unroll
    for (int st = 0; st < 8; st++) {
        uint32_t ko = kb0 + (uint32_t)st * 64;
        uint2 bb[6][2];
#pragma unroll
        for (int t = 0; t < 6; t++) {
            const unsigned char* bp = Bsm + boff + (uint32_t)t * 8 * PB + ko;
            bb[t][0] = *(const uint2*)bp;
            bb[t][1] = *(const uint2*)(bp + 32);
        }
#pragma unroll
        for (int fr = 0; fr < 2; fr++) {
            const unsigned char* ap = Asm + aoff + (uint32_t)fr * 16 * PA + ko;
            uint2 a0 = *(const uint2*)ap;
            uint2 a1 = *(const uint2*)(ap + 8 * PA);
            uint2 a2 = *(const uint2*)(ap + 32);
            uint2 a3 = *(const uint2*)(ap + 8 * PA + 32);
#pragma unroll
            for (int t = 0; t < 6; t++) {
                mma16816(acc[fr][t], a0.x, a1.x, a2.x, a3.x, bb[t][0].x, bb[t][1].x);
                mma16816(acc[fr][t], a0.y, a1.y, a2.y, a3.y, bb[t][0].x, bb[t][1].x);
                mma16816(acc[fr][t], a0.x, a1.x, a2.x, a3.x, bb[t][0].y, bb[t][1].y);
            }
        }
    }
    __syncthreads();    // all smem reads of A/B done before Ps overwrite

    // ---- reduce halves into Ps (+b2 by half 0) ----
    if (half == 0) {
#pragma unroll
        for (int fr = 0; fr < 2; fr++) {
#pragma unroll
            for (int t = 0; t < 6; t++) {
                int mrow = m0 + fr * 16 + lr;
                int col  = n0 + t * 8 + lc * 2;
                float bx = s_b2[col], by = s_b2[col + 1];
                if (mrow < MR)
                    *(float2*)(Ps + mrow * LDP + col) =
                        make_float2(acc[fr][t][0] + bx, acc[fr][t][1] + by);
                if (mrow + 8 < MR)
                    *(float2*)(Ps + (mrow + 8) * LDP + col) =
                        make_float2(acc[fr][t][2] + bx, acc[fr][t][3] + by);
            }
        }
    }
    __syncthreads();
    if (half == 1) {
#pragma unroll
        for (int fr = 0; fr < 2; fr++) {
#pragma unroll
            for (int t = 0; t < 6; t++) {
                int mrow = m0 + fr * 16 + lr;
                int col  = n0 + t * 8 + lc * 2;
                if (mrow < MR) {
                    float2* p = (float2*)(Ps + mrow * LDP + col);
                    float2 v = *p;
                    v.x += acc[fr][t][0]; v.y += acc[fr][t][1];
                    *p = v;
                }
                if (mrow + 8 < MR) {
                    float2* p = (float2*)(Ps + (mrow + 8) * LDP + col);
                    float2 v = *p;
                    v.x += acc[fr][t][2]; v.y += acc[fr][t][3];
                    *p = v;
                }
            }
        }
    }
    __syncthreads();

    // ---- payoff ----
    for (int pr = tid; pr < ETILE * AOUT; pr += 512) {
        int el = pr / AOUT;
        int i  = pr - el * AOUT;
        const float* P0 = &Ps[el * LDP];
        const float* P1 = &Ps[(ETILE + el) * LDP];
        float a0[4], a1[4];
#pragma unroll
        for (int r = 0; r < 4; r++) {
            a0[r] = P0[24 * r + i];
            a1[r] = P1[24 * r + 12 + i];
        }
        float res[12];
#pragma unroll
        for (int j = 0; j < 12; j++) {
            float s = 0.f;
#pragma unroll
            for (int r = 0; r < 4; r++)
                s = fmaf(a0[r], P0[24 * r + 12 + j], fmaf(a1[r], P1[24 * r + j], s));
            res[j] = 0.5f * s;
        }
        float4* op = reinterpret_cast<float4*>(
            out + ((size_t)(b * E_ + e0 + el) * AOUT + i) * AOUT);
        op[0] = make_float4(res[0], res[1], res[2],  res[3]);
        op[1] = make_float4(res[4], res[5], res[6],  res[7]);
        op[2] = make_float4(res[8], res[9], res[10], res[11]);
    }
}

// -------- launch --------
extern "C" void kernel_launch(void* const* d_in, const int* in_sizes, int n_in,
                              void* d_out, int out_size) {
    const float* h  = (const float*)d_in[0];
    const float* W1 = (const float*)d_in[1];
    const float* b1 = (const float*)d_in[2];
    const float* W2 = (const float*)d_in[3];
    const float* b2 = (const float*)d_in[4];
    const int*   ef = (const int*)d_in[5];
    const int*   et = (const int*)d_in[6];
    float* out = (float*)d_out;

    const int SMEM_A = (N_ * DH_ + JTILE * LDW1) * 4;      // 82,176 B

    cudaFuncSetAttribute(node_proj, cudaFuncAttributeMaxDynamicSharedMemorySize, SMEM_A);
    cudaFuncSetAttribute(edge_gemm, cudaFuncAttributeMaxDynamicSharedMemorySize, SMEM_EDGE);

    prep_edges<<<1, 256>>>(ef, et);
    prep_w2<<<(NO * KH + 255) / 256, 256>>>(W2);
    node_proj<<<dim3(KH / JTILE, B_), 256, SMEM_A>>>(h, W1, b1);
    edge_gemm<<<dim3(E_ / ETILE, B_), 512, SMEM_EDGE>>>(b2, out);
}

// round 9
// speedup vs baseline: 2.6374x; 1.1087x over previous
#include <cuda_runtime.h>
#include <cuda_bf16.h>
#include <cstdint>

#define B_    256
#define N_    32
#define DH_   128
#define E_    496
#define KH    256     // DIM_HID
#define NO    96      // DIM_OUT
#define AOUT  12
#define ETILE 62      // edges per block
#define MR    124     // 2*ETILE real rows
#define MPAD  128     // A rows allocated (warp tiles reach row 127)
#define LDP   98      // Ps pitch (floats, even -> float2 aligned)
#define JTILE 64
#define LDW1  257

#define A_REGION (MPAD * 1024)            // 131072
#define B_REGION (NO * 1024)              // 98304
#define SMEM_EDGE (A_REGION + B_REGION)   // 229376

// -------- device scratch --------
__device__ float g_u[2u * B_ * N_ * KH];                    // [s][b][n][k]; s0 has +b1 folded
__device__ __align__(16) unsigned char g_w2i[NO * 1024];    // W2 interleaved hi/lo bf16, XOR-swizzled
__device__ int g_ef[E_], g_et[E_];

// -------- mma.sync helper (bf16, f32 accum) --------
__device__ __forceinline__ void mma16816(float* c,
                                         uint32_t a0, uint32_t a1, uint32_t a2, uint32_t a3,
                                         uint32_t b0, uint32_t b1) {
    asm volatile(
        "mma.sync.aligned.m16n8k16.row.col.f32.bf16.bf16.f32 "
        "{%0,%1,%2,%3}, {%4,%5,%6,%7}, {%8,%9}, {%0,%1,%2,%3};"
        : "+f"(c[0]), "+f"(c[1]), "+f"(c[2]), "+f"(c[3])
        : "r"(a0), "r"(a1), "r"(a2), "r"(a3), "r"(b0), "r"(b1));
}

// -------- prep: normalize edge dtype (int32 vs int64) --------
__global__ void prep_edges(const int* __restrict__ efw, const int* __restrict__ etw) {
    int bad = 0;
    for (int t = threadIdx.x; t < E_; t += blockDim.x)
        if (t & 1)
            if (efw[t] != 0 || etw[t] != 0) bad = 1;
    int is32 = __syncthreads_or(bad);
    for (int e = threadIdx.x; e < E_; e += blockDim.x) {
        g_ef[e] = is32 ? efw[e] : efw[2 * e];
        g_et[e] = is32 ? etw[e] : etw[2 * e];
    }
}

// -------- prep: W2 -> interleaved hi/lo bf16 cells, XOR-swizzled --------
__global__ void prep_w2(const float* __restrict__ W2) {
    int idx = blockIdx.x * 256 + threadIdx.x;    // n*256 + k
    if (idx >= NO * KH) return;
    int n = idx >> 8, k = idx & 255;
    float v = W2[idx];
    __nv_bfloat16 hi = __float2bfloat16(v);
    __nv_bfloat16 lo = __float2bfloat16(v - __bfloat162float(hi));
    uint32_t kp   = (uint32_t)(k >> 1);
    uint32_t phys = kp ^ (((uint32_t)n & 3u) << 2);
    uint32_t cell = (uint32_t)n * 1024 + phys * 8 + (uint32_t)(k & 1) * 2;
    *(__nv_bfloat16*)(g_w2i + cell)     = hi;
    *(__nv_bfloat16*)(g_w2i + cell + 4) = lo;
}

// -------- stage A: node projections (b1 folded into u1 plane) --------
__global__ void __launch_bounds__(256) node_proj(const float* __restrict__ h,
                                                 const float* __restrict__ W1,
                                                 const float* __restrict__ b1) {
    extern __shared__ float smf[];
    float* hsA = smf;                   // 32*128
    float* w1s = smf + N_ * DH_;        // 64*LDW1

    int b  = blockIdx.y;
    int j0 = blockIdx.x * JTILE;
    int tid = threadIdx.x;

    for (int i = tid; i < N_ * DH_; i += 256)
        hsA[i] = h[(size_t)b * N_ * DH_ + i];
    for (int i = tid; i < JTILE * 256; i += 256) {
        int r = i >> 8, c = i & 255;
        w1s[r * LDW1 + c] = W1[(size_t)(j0 + r) * 256 + c];
    }
    __syncthreads();

    int jl = tid & 63;
    int ng = tid >> 6;
    float acc1[8], acc2[8];
#pragma unroll
    for (int i = 0; i < 8; i++) { acc1[i] = 0.f; acc2[i] = 0.f; }

    const float* w1row = &w1s[jl * LDW1];
    const float* hbase = &hsA[ng * 8 * DH_];
#pragma unroll 4
    for (int k = 0; k < DH_; k++) {
        float wa = w1row[k];
        float wb = w1row[k + 128];
#pragma unroll
        for (int nn = 0; nn < 8; nn++) {
            float hv = hbase[nn * DH_ + k];
            acc1[nn] = fmaf(wa, hv, acc1[nn]);
            acc2[nn] = fmaf(wb, hv, acc2[nn]);
        }
    }
    int j = j0 + jl;
    float b1v = b1[j];
#pragma unroll
    for (int nn = 0; nn < 8; nn++) {
        int n = ng * 8 + nn;
        g_u[(size_t)(b * N_ + n) * KH + j] = acc1[nn] + b1v;
        g_u[(size_t)B_ * N_ * KH + (size_t)(b * N_ + n) * KH + j] = acc2[nn];
    }
}

// -------- stage B: HMMA bf16x3 GEMM (16 warps, full-K, swizzled) + payoff --------
__global__ void __launch_bounds__(512, 1) edge_gemm(const float* __restrict__ b2,
                                                    float* __restrict__ out) {
    extern __shared__ unsigned char sm[];
    unsigned char* Asm = sm;                    // MPAD rows x 1024B (hi/lo interleaved, swizzled)
    unsigned char* Bsm = sm + A_REGION;         // NO rows x 1024B (swizzled)
    float* su1 = (float*)Bsm;                   // u staging lives in B region pre-copy
    float* su2 = su1 + N_ * KH;
    float* Ps  = (float*)Asm;                   // P result reuses A region post-MMA

    __shared__ int s_ef[ETILE], s_et[ETILE];
    __shared__ float s_b2[NO];

    int b = blockIdx.y, e0 = blockIdx.x * ETILE;
    int tid = threadIdx.x;
    int wid = tid >> 5, lid = tid & 31;

    if (tid < ETILE) { s_ef[tid] = g_ef[e0 + tid]; s_et[tid] = g_et[e0 + tid]; }
    if (tid >= 128 && tid < 128 + NO) s_b2[tid - 128] = b2[tid - 128];

    // ---- stage u planes into SMEM (coalesced) ----
    {
        const float4* gp1 = (const float4*)(g_u + (size_t)b * N_ * KH);
        const float4* gp2 = (const float4*)(g_u + (size_t)B_ * N_ * KH + (size_t)b * N_ * KH);
        float4* d1 = (float4*)su1;
        float4* d2 = (float4*)su2;
        for (int i = tid; i < N_ * KH / 4; i += 512) { d1[i] = gp1[i]; d2[i] = gp2[i]; }
    }
    __syncthreads();

    // ---- build A: relu(u1[f]+u2[t]) -> interleaved hi/lo cells, XOR-swizzled ----
    for (int i = tid; i < MR * (KH / 2); i += 512) {
        int m = i >> 7, kp = i & 127;
        int el = (m < ETILE) ? m : m - ETILE;
        int nf, nt;
        if (m < ETILE) { nf = s_ef[el]; nt = s_et[el]; }
        else           { nf = s_et[el]; nt = s_ef[el]; }
        float2 ua = *(const float2*)(su1 + nf * KH + 2 * kp);
        float2 ub = *(const float2*)(su2 + nt * KH + 2 * kp);
        float v0 = fmaxf(ua.x + ub.x, 0.f), v1 = fmaxf(ua.y + ub.y, 0.f);
        __nv_bfloat16 h0 = __float2bfloat16(v0), h1 = __float2bfloat16(v1);
        float r0 = v0 - __bfloat162float(h0), r1 = v1 - __bfloat162float(h1);
        __nv_bfloat16 l0 = __float2bfloat16(r0), l1 = __float2bfloat16(r1);
        uint2 cell;
        cell.x = ((uint32_t)__bfloat16_as_ushort(h1) << 16) | __bfloat16_as_ushort(h0);
        cell.y = ((uint32_t)__bfloat16_as_ushort(l1) << 16) | __bfloat16_as_ushort(l0);
        uint32_t phys = (uint32_t)kp ^ (((uint32_t)m & 3u) << 2);
        *(uint2*)(Asm + (uint32_t)m * 1024 + phys * 8) = cell;
    }
    __syncthreads();    // A built before u staging area is overwritten by B

    // ---- copy B (pre-swizzled) global -> SMEM, flat 96KB ----
    {
        const float4* gb = (const float4*)g_w2i;
        float4* db = (float4*)Bsm;
        for (int i = tid; i < B_REGION / 16; i += 512) db[i] = gb[i];
    }
    __syncthreads();

    // ---- HMMA: 16 warps, warp tile m32 x n24, full K=256, double-buffered ----
    int m0 = (wid >> 2) * 32;
    int n0 = (wid & 3) * 24;
    int lr = lid >> 2;              // 0..7
    int lc = lid & 3;               // 0..3
    uint32_t x4 = ((uint32_t)lr & 3u) << 2;
    uint32_t q  = (uint32_t)lc | (x4 & 4u);
    uint32_t x8 = x4 & 8u;

    const unsigned char* arow0 = Asm + (uint32_t)(m0 + lr) * 1024;
    const unsigned char* arow1 = arow0 + 8 * 1024;
    const unsigned char* arow2 = arow0 + 16 * 1024;
    const unsigned char* arow3 = arow0 + 24 * 1024;
    const unsigned char* brow0 = Bsm + (uint32_t)(n0 + lr) * 1024;
    const unsigned char* brow1 = brow0 + 8 * 1024;
    const unsigned char* brow2 = brow0 + 16 * 1024;

    float acc[2][3][4];
#pragma unroll
    for (int fr = 0; fr < 2; fr++)
#pragma unroll
        for (int t = 0; t < 3; t++)
#pragma unroll
            for (int c = 0; c < 4; c++) acc[fr][t][c] = 0.f;

    uint2 Af[2][8];     // [buf][fr*4 + {a0,a1,a2,a3}]
    uint2 Bf[2][6];     // [buf][t*2 + {b0,b1}]

#define LOAD_FRAGS(buf, st_) do {                                              \
        uint32_t off0 = ((((uint32_t)(st_) << 3) ^ x8) | q) << 3;              \
        uint32_t off4 = off0 ^ 32u;                                            \
        Af[buf][0] = *(const uint2*)(arow0 + off0);                            \
        Af[buf][1] = *(const uint2*)(arow1 + off0);                            \
        Af[buf][2] = *(const uint2*)(arow0 + off4);                            \
        Af[buf][3] = *(const uint2*)(arow1 + off4);                            \
        Af[buf][4] = *(const uint2*)(arow2 + off0);                            \
        Af[buf][5] = *(const uint2*)(arow3 + off0);                            \
        Af[buf][6] = *(const uint2*)(arow2 + off4);                            \
        Af[buf][7] = *(const uint2*)(arow3 + off4);                            \
        Bf[buf][0] = *(const uint2*)(brow0 + off0);                            \
        Bf[buf][1] = *(const uint2*)(brow0 + off4);                            \
        Bf[buf][2] = *(const uint2*)(brow1 + off0);                            \
        Bf[buf][3] = *(const uint2*)(brow1 + off4);                            \
        Bf[buf][4] = *(const uint2*)(brow2 + off0);                            \
        Bf[buf][5] = *(const uint2*)(brow2 + off4);                            \
    } while (0)

    LOAD_FRAGS(0, 0);
#pragma unroll
    for (int st = 0; st < 16; st++) {
        int cur = st & 1;
        if (st < 15) LOAD_FRAGS(cur ^ 1, st + 1);
#pragma unroll
        for (int fr = 0; fr < 2; fr++) {
            uint2 a0 = Af[cur][fr * 4 + 0];
            uint2 a1 = Af[cur][fr * 4 + 1];
            uint2 a2 = Af[cur][fr * 4 + 2];
            uint2 a3 = Af[cur][fr * 4 + 3];
#pragma unroll
            for (int t = 0; t < 3; t++) {
                uint2 b0 = Bf[cur][t * 2 + 0];
                uint2 b1 = Bf[cur][t * 2 + 1];
                mma16816(acc[fr][t], a0.x, a1.x, a2.x, a3.x, b0.x, b1.x);
                mma16816(acc[fr][t], a0.y, a1.y, a2.y, a3.y, b0.x, b1.x);
                mma16816(acc[fr][t], a0.x, a1.x, a2.x, a3.x, b0.y, b1.y);
            }
        }
    }
#undef LOAD_FRAGS

    __syncthreads();    // all smem reads of A/B done before Ps overwrite

    // ---- epilogue: direct store acc (+b2) into Ps ----
#pragma unroll
    for (int fr = 0; fr < 2; fr++) {
#pragma unroll
        for (int t = 0; t < 3; t++) {
            int mrow = m0 + fr * 16 + lr;
            int col  = n0 + t * 8 + lc * 2;
            float bx = s_b2[col], by = s_b2[col + 1];
            if (mrow < MR)
                *(float2*)(Ps + mrow * LDP + col) =
                    make_float2(acc[fr][t][0] + bx, acc[fr][t][1] + by);
            if (mrow + 8 < MR)
                *(float2*)(Ps + (mrow + 8) * LDP + col) =
                    make_float2(acc[fr][t][2] + bx, acc[fr][t][3] + by);
        }
    }
    __syncthreads();

    // ---- payoff ----
    for (int pr = tid; pr < ETILE * AOUT; pr += 512) {
        int el = pr / AOUT;
        int i  = pr - el * AOUT;
        const float* P0 = &Ps[el * LDP];
        const float* P1 = &Ps[(ETILE + el) * LDP];
        float a0[4], a1[4];
#pragma unroll
        for (int r = 0; r < 4; r++) {
            a0[r] = P0[24 * r + i];
            a1[r] = P1[24 * r + 12 + i];
        }
        float res[12];
#pragma unroll
        for (int j = 0; j < 12; j++) {
            float s = 0.f;
#pragma unroll
            for (int r = 0; r < 4; r++)
                s = fmaf(a0[r], P0[24 * r + 12 + j], fmaf(a1[r], P1[24 * r + j], s));
            res[j] = 0.5f * s;
        }
        float4* op = reinterpret_cast<float4*>(
            out + ((size_t)(b * E_ + e0 + el) * AOUT + i) * AOUT);
        op[0] = make_float4(res[0], res[1], res[2],  res[3]);
        op[1] = make_float4(res[4], res[5], res[6],  res[7]);
        op[2] = make_float4(res[8], res[9], res[10], res[11]);
    }
}

// -------- launch --------
extern "C" void kernel_launch(void* const* d_in, const int* in_sizes, int n_in,
                              void* d_out, int out_size) {
    const float* h  = (const float*)d_in[0];
    const float* W1 = (const float*)d_in[1];
    const float* b1 = (const float*)d_in[2];
    const float* W2 = (const float*)d_in[3];
    const float* b2 = (const float*)d_in[4];
    const int*   ef = (const int*)d_in[5];
    const int*   et = (const int*)d_in[6];
    float* out = (float*)d_out;

    const int SMEM_A = (N_ * DH_ + JTILE * LDW1) * 4;      // 82,176 B

    cudaFuncSetAttribute(node_proj, cudaFuncAttributeMaxDynamicSharedMemorySize, SMEM_A);
    cudaFuncSetAttribute(edge_gemm, cudaFuncAttributeMaxDynamicSharedMemorySize, SMEM_EDGE);

    prep_edges<<<1, 256>>>(ef, et);
    prep_w2<<<(NO * KH + 255) / 256, 256>>>(W2);
    node_proj<<<dim3(KH / JTILE, B_), 256, SMEM_A>>>(h, W1, b1);
    edge_gemm<<<dim3(E_ / ETILE, B_), 512, SMEM_EDGE>>>(b2, out);
}